// round 11
// baseline (speedup 1.0000x reference)
#include <cuda_runtime.h>
#include <cstdint>

// Problem constants
#define BB   64
#define II   128
#define TT   1024
#define HH   256
#define G4   1024   // 4*H

// ---------------- scratch: pre-activations pre[b][t][4H] (256 MB) ----------
__device__ float g_pre[(size_t)BB * TT * G4];

// ---------------- helpers ----------------
__device__ __forceinline__ void ffma2(unsigned long long& d,
                                      unsigned long long a,
                                      unsigned long long b) {
    asm("fma.rn.f32x2 %0, %1, %2, %0;" : "+l"(d) : "l"(a), "l"(b));
}
__device__ __forceinline__ unsigned long long packf2(float a, float b) {
    unsigned long long r;
    asm("mov.b64 %0, {%1, %2};" : "=l"(r) : "f"(a), "f"(b));
    return r;
}
__device__ __forceinline__ float f2lo(unsigned long long v) {
    return __uint_as_float((unsigned)(v & 0xffffffffull));
}
__device__ __forceinline__ float f2hi(unsigned long long v) {
    return __uint_as_float((unsigned)(v >> 32));
}
__device__ __forceinline__ uint32_t mapa_rank(uint32_t addr, uint32_t r) {
    uint32_t out;
    asm("mapa.shared::cluster.u32 %0, %1, %2;" : "=r"(out) : "r"(addr), "r"(r));
    return out;
}
#define CLUSTER_SYNC() do { \
    asm volatile("barrier.cluster.arrive.aligned;" ::: "memory"); \
    asm volatile("barrier.cluster.wait.aligned;"   ::: "memory"); \
} while (0)

#define MBAR_INIT(addr, cnt) \
    asm volatile("mbarrier.init.shared.b64 [%0], %1;" :: "r"(addr), "r"(cnt) : "memory")
#define MBAR_EXPECT_TX(addr, bytes) \
    asm volatile("mbarrier.arrive.expect_tx.shared.b64 _, [%0], %1;" \
                 :: "r"(addr), "r"(bytes) : "memory")

__device__ __forceinline__ void mbar_wait_acq(uint32_t mbar, uint32_t parity) {
    asm volatile(
        "{\n\t"
        ".reg .pred P;\n\t"
        "MWL_%=:\n\t"
        "mbarrier.try_wait.parity.acquire.cluster.shared::cta.b64 P, [%0], %1, 0x989680;\n\t"
        "@!P bra MWL_%=;\n\t"
        "}"
        :: "r"(mbar), "r"(parity) : "memory");
}

// DSMEM bulk copy: local smem -> peer smem, complete_tx on peer's mbarrier.
__device__ __forceinline__ void bulk_copy_cluster(uint32_t dst_cluster,
                                                  uint32_t src_cta,
                                                  uint32_t bytes,
                                                  uint32_t mbar_cluster) {
    asm volatile(
        "cp.async.bulk.shared::cluster.shared::cta.mbarrier::complete_tx::bytes "
        "[%0], [%1], %2, [%3];"
        :: "r"(dst_cluster), "r"(src_cta), "r"(bytes), "r"(mbar_cluster)
        : "memory");
}

// ============================================================================
// Phase 1: pre[b][t][g] = sum_i x[b,i,t] * W_ih[g,i] + b_ih[g] + b_hh[g]
// CTA = 64t x 128g, 256 threads; FFMA2 over gate-pairs (w-pairs from float4).
// ============================================================================
__global__ __launch_bounds__(256) void lstm_pre_kernel(
    const float* __restrict__ x,
    const float* __restrict__ W_ih,
    const float* __restrict__ b_ih,
    const float* __restrict__ b_hh)
{
    __shared__ __align__(16) float xs[32][68];    // [k][t]
    __shared__ __align__(16) float ws[32][136];   // [k][g], rows 16B-aligned

    const int tid = threadIdx.x;
    const int tx  = tid & 15;    // g-group (8 g each)
    const int ty  = tid >> 4;    // t-group (4 t each)

    const int t0 = blockIdx.x * 64;
    const int g0 = blockIdx.y * 128;
    const int b  = blockIdx.z;

    const int gcol = g0 + tx * 8;

    float bias[8];
#pragma unroll
    for (int ig = 0; ig < 8; ig++)
        bias[ig] = b_ih[gcol + ig] + b_hh[gcol + ig];

    unsigned long long acc[4][4];   // [t][gpair] lanes = (g even, g odd)
#pragma unroll
    for (int it = 0; it < 4; it++)
#pragma unroll
        for (int gpi = 0; gpi < 4; gpi++) acc[it][gpi] = 0ull;

    const size_t xbase = (size_t)b * II * TT;   // x[b, i, t] stride i = TT

    for (int kt = 0; kt < 4; kt++) {
#pragma unroll
        for (int idx = tid; idx < 32 * 64; idx += 256) {
            int k = idx >> 6, t = idx & 63;
            xs[k][t] = x[xbase + (size_t)(kt * 32 + k) * TT + t0 + t];
        }
#pragma unroll
        for (int idx = tid; idx < 32 * 128; idx += 256) {
            int k = idx & 31, g = idx >> 5;
            ws[k][g] = W_ih[(size_t)(g0 + g) * II + kt * 32 + k];
        }
        __syncthreads();

#pragma unroll
        for (int k = 0; k < 32; k++) {
            float4 xv = *(const float4*)&xs[k][ty * 4];
            ulonglong2 wA = *(const ulonglong2*)&ws[k][tx * 8];      // (g0,g1),(g2,g3)
            ulonglong2 wB = *(const ulonglong2*)&ws[k][tx * 8 + 4];  // (g4,g5),(g6,g7)
            float xr[4] = {xv.x, xv.y, xv.z, xv.w};
#pragma unroll
            for (int it = 0; it < 4; it++) {
                unsigned long long xx = packf2(xr[it], xr[it]);
                ffma2(acc[it][0], wA.x, xx);
                ffma2(acc[it][1], wA.y, xx);
                ffma2(acc[it][2], wB.x, xx);
                ffma2(acc[it][3], wB.y, xx);
            }
        }
        __syncthreads();
    }

#pragma unroll
    for (int it = 0; it < 4; it++) {
        size_t orow = ((size_t)b * TT + (t0 + ty * 4 + it)) * G4 + gcol;
        float4 o1, o2;
        o1.x = f2lo(acc[it][0]) + bias[0]; o1.y = f2hi(acc[it][0]) + bias[1];
        o1.z = f2lo(acc[it][1]) + bias[2]; o1.w = f2hi(acc[it][1]) + bias[3];
        o2.x = f2lo(acc[it][2]) + bias[4]; o2.y = f2hi(acc[it][2]) + bias[5];
        o2.z = f2lo(acc[it][3]) + bias[6]; o2.w = f2hi(acc[it][3]) + bias[7];
        *(float4*)&g_pre[orow]     = o1;
        *(float4*)&g_pre[orow + 4] = o2;
    }
}

// ============================================================================
// Phase 2: recurrent scan. Cluster of 8 CTAs = 4 batches; CTA rank owns units
// [32r,32r+32). Thread (u, gp, kp) holds 2 gate rows x 32-k slice in regs.
// h exchange: each step, ilanes stage 128 h floats (512B contiguous), then
// 8 threads issue ONE cp.async.bulk (512B) per peer -> 8 mbarrier arrivals
// per step (was 1024 st.async arrivals — the R9 bottleneck).
// h layout: [src_rank (stride 132 fl)][batch (32 fl)][unit] — bulk-copy dst
// contiguous AND conflict-free GEMV loads (kp*528 mod 128 = 16*kp).
// ============================================================================
#define RSLAB   132                  // floats per rank slab (128 + 4 pad)
#define HBUFSZ  (8 * RSLAB)          // 1056 floats per buffer
#define TXBYTES 4096                 // 8 peers * 512B per step

__global__ void __cluster_dims__(8, 1, 1) __launch_bounds__(512)
lstm_rec_kernel(const float* __restrict__ W_hh, float* __restrict__ out)
{
    __shared__ __align__(16) float h_s[2][HBUFSZ];
    __shared__ __align__(16) float stage[2][128];
    __shared__ __align__(8) unsigned long long mbar[2];

    const int tid = threadIdx.x;
    const int kp  = tid & 7;          // k-slice 0..7 (32 k each)
    const int gp  = (tid >> 3) & 1;   // gate-pair: 0 -> (i,f), 1 -> (g,o)
    const int u   = tid >> 4;         // unit 0..31 within rank

    uint32_t rank;
    asm("mov.u32 %0, %%cluster_ctarank;" : "=r"(rank));
    const int clid = blockIdx.x >> 3;
    const int bg0  = clid * 4;
    const int ug   = (int)rank * 32 + u;

    // ---- W_hh: rows (gp*2, gp*2+1), k-slice [kp*32, +32), as f32x2 pairs ----
    unsigned long long W2[2][16];
#pragma unroll
    for (int g = 0; g < 2; g++) {
        const int row = (gp * 2 + g) * HH + ug;
        const float4* wr = (const float4*)(W_hh + (size_t)row * HH + kp * 32);
#pragma unroll
        for (int j = 0; j < 8; j++) {
            float4 v = wr[j];
            W2[g][2 * j]     = packf2(v.x, v.y);
            W2[g][2 * j + 1] = packf2(v.z, v.w);
        }
    }

    // zero buffer 0 (read at t=0)
    for (int i = tid; i < HBUFSZ; i += 512) h_s[0][i] = 0.0f;

    const uint32_t hs_addr = (uint32_t)__cvta_generic_to_shared(&h_s[0][0]);
    const uint32_t st_addr = (uint32_t)__cvta_generic_to_shared(&stage[0][0]);
    const uint32_t mb_addr = (uint32_t)__cvta_generic_to_shared(&mbar[0]);

    if (tid == 0) {
        MBAR_INIT(mb_addr, 1);
        MBAR_INIT(mb_addr + 8, 1);
        MBAR_EXPECT_TX(mb_addr, TXBYTES);        // first waited at t=2
        MBAR_EXPECT_TX(mb_addr + 8, TXBYTES);    // first waited at t=1
    }
    __syncthreads();
    CLUSTER_SYNC();   // all peers zeroed + armed before any bulk copy flies

    // lane (gp,kp) owns gate = gp*2 + (kp>>2), batch = kp&3 after reduce
    const int gate_lane = gp * 2 + (kp >> 2);
    const int b_lane    = kp & 3;
    const float* pp = g_pre + ((size_t)(bg0 + b_lane) * TT) * G4
                            + gate_lane * HH + ug;
    float pre_next = pp[0];

    const bool ilane = (gp == 0) && (kp < 4);     // owns cell (u, b=kp)
    float c_reg = 0.0f;
    const size_t outbase = ((size_t)(bg0 + kp) * HH + ug) * TT;

    // peer addresses for bulk copy (issued by tid<8; thread r targets rank r)
    const uint32_t peer_h  = mapa_rank(hs_addr, (uint32_t)tid & 7)
                             + rank * (RSLAB * 4);      // my slab in peer's buf
    const uint32_t peer_mb = mapa_rank(mb_addr, (uint32_t)tid & 7);

    uint32_t par0 = 0, par1 = 0;

    for (int t = 0; t < TT; t++) {
        // ---- wait for this step's h (8 bulk copies landed); re-arm ----
        if (t > 0) {
            if (t & 1) {
                mbar_wait_acq(mb_addr + 8, par1); par1 ^= 1;
                if (tid == 0) MBAR_EXPECT_TX(mb_addr + 8, TXBYTES);
            } else {
                mbar_wait_acq(mb_addr, par0); par0 ^= 1;
                if (tid == 0) MBAR_EXPECT_TX(mb_addr, TXBYTES);
            }
        }
        const float pre_cur = pre_next;
        pre_next = (t + 1 < TT) ? pp[(size_t)(t + 1) * G4] : 0.0f;

        // ---- GEMV: 2 gates x 4 batches over 32-k slice (8 LDS.128 / batch) ----
        const float* hb = &h_s[t & 1][kp * RSLAB];
        float A[2][4];
#pragma unroll
        for (int b = 0; b < 4; b++) {
            const ulonglong2* hv = (const ulonglong2*)(hb + b * 32);
            unsigned long long a00 = 0ull, a01 = 0ull, a10 = 0ull, a11 = 0ull;
#pragma unroll
            for (int j = 0; j < 8; j++) {
                ulonglong2 h2 = hv[j];
                ffma2(a00, W2[0][2 * j],     h2.x);
                ffma2(a01, W2[0][2 * j + 1], h2.y);
                ffma2(a10, W2[1][2 * j],     h2.x);
                ffma2(a11, W2[1][2 * j + 1], h2.y);
            }
            A[0][b] = (f2lo(a00) + f2hi(a00)) + (f2lo(a01) + f2hi(a01));
            A[1][b] = (f2lo(a10) + f2hi(a10)) + (f2lo(a11) + f2hi(a11));
        }

        // ---- reduce-scatter over 8 kp lanes: 7 shfls ----
        const int sel = kp >> 2;
        float B0[4];
#pragma unroll
        for (int b = 0; b < 4; b++) {
            float sendv = sel ? A[0][b] : A[1][b];
            float keepv = sel ? A[1][b] : A[0][b];
            B0[b] = keepv + __shfl_xor_sync(0xffffffffu, sendv, 4);
        }
        const int t1 = (kp >> 1) & 1;
        {
            float s0 = t1 ? B0[0] : B0[2];
            float s1 = t1 ? B0[1] : B0[3];
            float k0 = t1 ? B0[2] : B0[0];
            float k1 = t1 ? B0[3] : B0[1];
            B0[0] = k0 + __shfl_xor_sync(0xffffffffu, s0, 2);
            B0[1] = k1 + __shfl_xor_sync(0xffffffffu, s1, 2);
        }
        const int tb0 = kp & 1;
        float sendv = tb0 ? B0[0] : B0[1];
        float keepv = tb0 ? B0[1] : B0[0];
        float gv = keepv + __shfl_xor_sync(0xffffffffu, sendv, 1) + pre_cur;

        // ---- distributed activation: sigmoid, or tanh = 2*sigmoid(2x)-1 ----
        const bool isg = (gate_lane == 2);
        float sarg = isg ? 2.0f * gv : gv;
        float e = __expf(-sarg);
        float y = __frcp_rn(1.0f + e);
        float act = isg ? fmaf(2.0f, y, -1.0f) : y;

        // gather f,g,o to the i-lane (all lanes execute shfls)
        float fv = __shfl_xor_sync(0xffffffffu, act, 4);
        float gg = __shfl_xor_sync(0xffffffffu, act, 8);
        float ov = __shfl_xor_sync(0xffffffffu, act, 12);

        if (ilane) {
            c_reg = fmaf(fv, c_reg, act * gg);
            float ax  = fabsf(c_reg);
            float tt2 = __expf(-2.0f * ax);
            float th  = (1.0f - tt2) * __frcp_rn(1.0f + tt2);
            th = copysignf(th, c_reg);
            float h = ov * th;
            out[outbase + t] = fmaxf(h, 0.0f);
            stage[t & 1][kp * 32 + u] = h;      // contiguous 512B staging
        }
        __syncthreads();   // staging complete before copies read it

        if (t + 1 < TT && tid < 8) {
            asm volatile("fence.proxy.async.shared::cta;" ::: "memory");
            const uint32_t boff = ((t + 1) & 1) ? (uint32_t)(HBUFSZ * 4) : 0u;
            const uint32_t moff = (uint32_t)(((t + 1) & 1) << 3);
            bulk_copy_cluster(peer_h + boff,
                              st_addr + (uint32_t)((t & 1) * 512),
                              512u,
                              peer_mb + moff);
        }
    }
    CLUSTER_SYNC();   // no CTA exits while peers' copies may still be in flight
}

// ============================================================================
extern "C" void kernel_launch(void* const* d_in, const int* in_sizes, int n_in,
                              void* d_out, int out_size)
{
    const float* x    = (const float*)d_in[0];
    const float* W_ih = (const float*)d_in[1];
    const float* W_hh = (const float*)d_in[2];
    const float* b_ih = (const float*)d_in[3];
    const float* b_hh = (const float*)d_in[4];
    float* out = (float*)d_out;

    dim3 g1(TT / 64, G4 / 128, BB);   // 16 x 8 x 64
    lstm_pre_kernel<<<g1, 256>>>(x, W_ih, b_ih, b_hh);

    lstm_rec_kernel<<<128, 512>>>(W_hh, out);   // 16 clusters of 8 CTAs
}